// round 2
// baseline (speedup 1.0000x reference)
#include <cuda_runtime.h>

// MoE conditional FFN: T=16 tokens, TOP_K=2, E=8 experts, H=1024, I=2816, fp32.
// Expert-major grouping so each used expert's weights stream from HBM exactly once.
// Phase 1: h[pair, o] = silu(gate[e,o,:]·x[t]) * (down[e,o,:]·x[t])
// Phase 2: out[pair, hh] = up[e, hh, :] · h[pair, :]

#define NTOK   16
#define TOPK   2
#define NPAIR  (NTOK * TOPK)       // 32
#define HID    1024
#define INTER  2816
#define NEXP   8

// Intermediate activations (32 * 2816 floats = 360 KB). Static device scratch
// (no allocation, graph-capture safe).
__device__ float g_h[NPAIR * INTER];

// ---------------------------------------------------------------------------
// Phase 1: gate & down GEMVs + SiLU-mul.
// grid = (INTER/32, NEXP), block = 256 (8 warps). Warp handles 4 rows.
// ---------------------------------------------------------------------------
__global__ __launch_bounds__(256, 2)
void moe_phase1(const float* __restrict__ x,        // [T, H]
                const int*   __restrict__ eidx,     // [T, TOPK]
                const float* __restrict__ gate,     // [E, I, H]
                const float* __restrict__ down)     // [E, I, H]
{
    const int e = blockIdx.y;

    __shared__ int s_cnt;
    __shared__ int s_pair[NPAIR];
    if (threadIdx.x == 0) {
        int c = 0;
        #pragma unroll
        for (int i = 0; i < NPAIR; i++)
            if (eidx[i] == e) s_pair[c++] = i;
        s_cnt = c;
    }
    __syncthreads();
    const int cnt = s_cnt;
    if (cnt == 0) return;

    const int warp = threadIdx.x >> 5;
    const int lane = threadIdx.x & 31;
    const int row0 = blockIdx.x * 32 + warp * 4;

    const float4* gate4 = reinterpret_cast<const float4*>(gate + (size_t)e * INTER * HID);
    const float4* down4 = reinterpret_cast<const float4*>(down + (size_t)e * INTER * HID);
    // Each row = HID/4 = 256 float4; lane covers 8 of them (stride 32).

    for (int rr = 0; rr < 4; rr++) {
        const int row = row0 + rr;
        if (row >= INTER) return;
        const float4* gr = gate4 + (size_t)row * (HID / 4);
        const float4* dr = down4 + (size_t)row * (HID / 4);

        float4 g4[8], d4[8];
        #pragma unroll
        for (int j = 0; j < 8; j++) {
            g4[j] = gr[lane + 32 * j];
            d4[j] = dr[lane + 32 * j];
        }

        for (int p = 0; p < cnt; p++) {
            const int pa = s_pair[p];
            const int t  = pa >> 1;   // pair index = t*TOPK + a
            const float4* xr = reinterpret_cast<const float4*>(x + (size_t)t * HID);

            float ag = 0.f, ad = 0.f;
            #pragma unroll
            for (int j = 0; j < 8; j++) {
                const float4 x4 = xr[lane + 32 * j];
                ag = fmaf(g4[j].x, x4.x, ag);
                ag = fmaf(g4[j].y, x4.y, ag);
                ag = fmaf(g4[j].z, x4.z, ag);
                ag = fmaf(g4[j].w, x4.w, ag);
                ad = fmaf(d4[j].x, x4.x, ad);
                ad = fmaf(d4[j].y, x4.y, ad);
                ad = fmaf(d4[j].z, x4.z, ad);
                ad = fmaf(d4[j].w, x4.w, ad);
            }
            #pragma unroll
            for (int off = 16; off; off >>= 1) {
                ag += __shfl_xor_sync(0xFFFFFFFFu, ag, off);
                ad += __shfl_xor_sync(0xFFFFFFFFu, ad, off);
            }
            if (lane == 0) {
                const float s = ag / (1.f + __expf(-ag));   // silu(gate)
                g_h[(size_t)pa * INTER + row] = s * ad;
            }
        }
    }
}

// ---------------------------------------------------------------------------
// Phase 2: out[pair, hh] = up[e, hh, :] . h[pair, :]
// grid = (HID/32, NEXP), block = 256 (8 warps). Warp handles 4 output rows.
// ---------------------------------------------------------------------------
__global__ __launch_bounds__(256, 2)
void moe_phase2(const int*   __restrict__ eidx,     // [T, TOPK]
                const float* __restrict__ up,       // [E, H, I]
                float*       __restrict__ out)      // [T, TOPK, H]
{
    const int e = blockIdx.y;

    __shared__ int s_cnt;
    __shared__ int s_pair[NPAIR];
    if (threadIdx.x == 0) {
        int c = 0;
        #pragma unroll
        for (int i = 0; i < NPAIR; i++)
            if (eidx[i] == e) s_pair[c++] = i;
        s_cnt = c;
    }
    __syncthreads();
    const int cnt = s_cnt;
    if (cnt == 0) return;

    const int warp = threadIdx.x >> 5;
    const int lane = threadIdx.x & 31;
    const int h0 = blockIdx.x * 32 + warp * 4;

    const float4* up4 = reinterpret_cast<const float4*>(up + (size_t)e * HID * INTER);
    // Each row = INTER/4 = 704 float4; lane covers 22 of them (stride 32).

    for (int rr = 0; rr < 4; rr++) {
        const int hh = h0 + rr;
        if (hh >= HID) return;
        const float4* ur = up4 + (size_t)hh * (INTER / 4);

        for (int p = 0; p < cnt; p++) {
            const int pa = s_pair[p];
            const float4* hr = reinterpret_cast<const float4*>(g_h + (size_t)pa * INTER);

            float acc = 0.f;
            #pragma unroll
            for (int j = 0; j < 22; j++) {
                const float4 u4 = ur[lane + 32 * j];
                const float4 h4 = hr[lane + 32 * j];
                acc = fmaf(u4.x, h4.x, acc);
                acc = fmaf(u4.y, h4.y, acc);
                acc = fmaf(u4.z, h4.z, acc);
                acc = fmaf(u4.w, h4.w, acc);
            }
            #pragma unroll
            for (int off = 16; off; off >>= 1)
                acc += __shfl_xor_sync(0xFFFFFFFFu, acc, off);
            if (lane == 0)
                out[(size_t)pa * HID + hh] = acc;
        }
    }
}

// ---------------------------------------------------------------------------
// Launch. Inputs (metadata order): x, expert_indices, gate_proj, up_proj, down_proj.
// Output: float32 [T, TOPK, H].
// ---------------------------------------------------------------------------
extern "C" void kernel_launch(void* const* d_in, const int* in_sizes, int n_in,
                              void* d_out, int out_size)
{
    const float* x    = (const float*)d_in[0];
    const int*   eidx = (const int*)  d_in[1];
    const float* gate = (const float*)d_in[2];
    const float* up   = (const float*)d_in[3];
    const float* down = (const float*)d_in[4];
    float* out = (float*)d_out;

    dim3 g1(INTER / 32, NEXP);   // 88 x 8
    moe_phase1<<<g1, 256>>>(x, eidx, gate, down);

    dim3 g2(HID / 32, NEXP);     // 32 x 8
    moe_phase2<<<g2, 256>>>(eidx, up, out);
}